// round 1
// baseline (speedup 1.0000x reference)
#include <cuda_runtime.h>
#include <math.h>

#define NN 100000
#define NE 3200000
#define FIN 512
#define HD 16
#define NC 40

// ---------------- device scratch (static: no runtime alloc) ----------------
__device__ int   g_is64;          // 1 if edge_index is int64, 0 if int32
__device__ int   g_deg[NN];       // in-degree (excl. self loop)
__device__ int   g_off[NN + 1];   // CSR offsets (by dst)
__device__ int   g_cur[NN];       // scatter cursors
__device__ int   g_bsum[128];     // block sums for scan
__device__ int   g_src[NE];       // src node per edge, grouped by dst
__device__ float g_dinv[NN];      // 1/sqrt(deg+1)
__device__ float g_h1s[NN * HD];  // (x@W1) * dinv   (pre-scaled)
__device__ float g_rs[NN * HD];   // relu(A_hat h1 + b1) * dinv

// ---------------- edge index loader (int32/int64 agnostic) ----------------
__device__ __forceinline__ int load_idx(const void* ei, long long pos) {
    if (g_is64) return (int)((const long long*)ei)[pos];
    return ((const int*)ei)[pos];
}

// Detect dtype: int64 node ids < 2^31 => every odd 32-bit word is 0.
__global__ void k_detect(const int* __restrict__ ei32) {
    int lane = threadIdx.x;
    int w = ei32[2 * lane + 1];
    unsigned nz = __ballot_sync(0xffffffffu, w != 0);
    if (lane == 0) g_is64 = (nz == 0) ? 1 : 0;
}

__global__ void k_zero_deg() {
    int i = blockIdx.x * 256 + threadIdx.x;
    if (i < NN) g_deg[i] = 0;
}

__global__ void k_hist(const void* __restrict__ ei) {
    int e = blockIdx.x * 256 + threadIdx.x;
    if (e < NE) {
        int col = load_idx(ei, (long long)NE + e);
        atomicAdd(&g_deg[col], 1);
    }
}

// Per-1024-block inclusive scan of degrees -> g_off[i+1] (partial), block sums.
__global__ void k_scan1() {
    int i = blockIdx.x * 1024 + threadIdx.x;
    int val = (i < NN) ? g_deg[i] : 0;
    int lane = threadIdx.x & 31, wid = threadIdx.x >> 5;
    int x = val;
#pragma unroll
    for (int o = 1; o < 32; o <<= 1) {
        int y = __shfl_up_sync(0xffffffffu, x, o);
        if (lane >= o) x += y;
    }
    __shared__ int wsum[32];
    if (lane == 31) wsum[wid] = x;
    __syncthreads();
    if (wid == 0) {
        int w = wsum[lane];
#pragma unroll
        for (int o = 1; o < 32; o <<= 1) {
            int y = __shfl_up_sync(0xffffffffu, w, o);
            if (lane >= o) w += y;
        }
        wsum[lane] = w;
    }
    __syncthreads();
    int incl = x + (wid > 0 ? wsum[wid - 1] : 0);
    if (i < NN) g_off[i + 1] = incl;
    if (threadIdx.x == 1023) g_bsum[blockIdx.x] = incl;
}

// Scan of block sums (nb <= 128), single block Hillis-Steele.
__global__ void k_scan2(int nb) {
    __shared__ int s[128];
    int t = threadIdx.x;
    s[t] = (t < nb) ? g_bsum[t] : 0;
    __syncthreads();
#pragma unroll
    for (int o = 1; o < 128; o <<= 1) {
        int v = (t >= o) ? s[t - o] : 0;
        __syncthreads();
        s[t] += v;
        __syncthreads();
    }
    g_bsum[t] = s[t];
}

// Finalize offsets, cursors, dinv.
__global__ void k_scan3() {
    int i = blockIdx.x * 256 + threadIdx.x;
    if (i >= NN) return;
    int b = i >> 10;
    int add = b ? g_bsum[b - 1] : 0;
    int incl = g_off[i + 1] + add;
    g_off[i + 1] = incl;
    int d = g_deg[i];
    g_cur[i] = incl - d;
    g_dinv[i] = rsqrtf((float)(d + 1));
    if (i == 0) g_off[0] = 0;
}

__global__ void k_scatter(const void* __restrict__ ei) {
    int e = blockIdx.x * 256 + threadIdx.x;
    if (e < NE) {
        int row = load_idx(ei, e);
        int col = load_idx(ei, (long long)NE + e);
        int pos = atomicAdd(&g_cur[col], 1);
        g_src[pos] = row;
    }
}

// h1s[v] = (x[v] @ W1) * dinv[v].  Warp handles 4 rows; lanes parallel over K.
__global__ __launch_bounds__(256) void k_gemm1(const float* __restrict__ x,
                                               const float* __restrict__ W1) {
    __shared__ float Wt[HD * FIN];  // Wt[j*512 + k] = W1[k*16 + j]
    int tid = threadIdx.x;
    for (int idx = tid; idx < HD * FIN; idx += 256) {
        int j = idx >> 9;
        int k = idx & 511;
        Wt[idx] = W1[k * HD + j];
    }
    __syncthreads();

    int warp = tid >> 5, lane = tid & 31;
    int row0 = (blockIdx.x * 8 + warp) * 4;
    if (row0 >= NN) return;

    const float4* x4 = (const float4*)x;
    const float4* Wt4 = (const float4*)Wt;

    float acc[4][16];
#pragma unroll
    for (int r = 0; r < 4; r++)
#pragma unroll
        for (int j = 0; j < 16; j++) acc[r][j] = 0.f;

#pragma unroll
    for (int i = 0; i < 4; i++) {
        int k4 = i * 32 + lane;
        float4 xv[4];
#pragma unroll
        for (int r = 0; r < 4; r++)
            xv[r] = x4[(size_t)(row0 + r) * 128 + k4];
#pragma unroll
        for (int j = 0; j < 16; j++) {
            float4 wv = Wt4[j * 128 + k4];
#pragma unroll
            for (int r = 0; r < 4; r++) {
                acc[r][j] += xv[r].x * wv.x + xv[r].y * wv.y +
                             xv[r].z * wv.z + xv[r].w * wv.w;
            }
        }
    }

    // Cross-lane reduction distributing 16 features across lanes 0..15.
#pragma unroll
    for (int r = 0; r < 4; r++) {
#pragma unroll
        for (int f = 0; f < 16; f++)
            acc[r][f] += __shfl_xor_sync(0xffffffffu, acc[r][f], 16);
#pragma unroll
        for (int o = 8; o > 0; o >>= 1) {
            bool hi = (lane & o) != 0;
#pragma unroll
            for (int f = 0; f < o; f++) {
                float mine = hi ? acc[r][f] : acc[r][f + o];
                float got = __shfl_xor_sync(0xffffffffu, mine, o);
                float keep = hi ? acc[r][f + o] : acc[r][f];
                acc[r][f] = keep + got;
            }
        }
    }
    // lane l (l<16) now holds feature l in acc[r][0]
    if (lane < 16) {
#pragma unroll
        for (int r = 0; r < 4; r++) {
            float dv = g_dinv[row0 + r];
            g_h1s[(size_t)(row0 + r) * HD + lane] = acc[r][0] * dv;
        }
    }
}

// Aggregation 1: rs[v] = relu( (sum_in h1s + h1s[v]) * dinv[v] + b1 ) * dinv[v]
__global__ __launch_bounds__(256) void k_agg1(const float* __restrict__ b1) {
    int warp = (blockIdx.x * 256 + threadIdx.x) >> 5;
    if (warp >= NN) return;
    int v = warp;
    int lane = threadIdx.x & 31;
    int half = lane >> 4;
    int j = lane & 15;
    int start = g_off[v], end = g_off[v + 1];
    float sum = 0.f;
    int e = start + half;
    for (; e + 6 < end; e += 8) {
        int s0 = g_src[e], s1 = g_src[e + 2], s2 = g_src[e + 4], s3 = g_src[e + 6];
        float a0 = g_h1s[(size_t)s0 * HD + j];
        float a1 = g_h1s[(size_t)s1 * HD + j];
        float a2 = g_h1s[(size_t)s2 * HD + j];
        float a3 = g_h1s[(size_t)s3 * HD + j];
        sum += (a0 + a1) + (a2 + a3);
    }
    for (; e < end; e += 2) sum += g_h1s[(size_t)g_src[e] * HD + j];
    sum += __shfl_xor_sync(0xffffffffu, sum, 16);
    float dv = g_dinv[v];
    float a = (sum + g_h1s[(size_t)v * HD + j]) * dv + b1[j];
    float r = fmaxf(a, 0.f);
    if (half == 0) g_rs[(size_t)v * HD + j] = r * dv;
}

// Aggregation 2 fused with 16->40 GEMM + log_softmax.
__global__ __launch_bounds__(256) void k_agg2_out(const float* __restrict__ W2,
                                                 const float* __restrict__ b2,
                                                 float* __restrict__ out) {
    __shared__ float W2s[HD * NC];
    int tid = threadIdx.x;
    for (int idx = tid; idx < HD * NC; idx += 256) W2s[idx] = W2[idx];
    __syncthreads();

    int warp = (blockIdx.x * 256 + tid) >> 5;
    if (warp >= NN) return;
    int v = warp;
    int lane = tid & 31;
    int half = lane >> 4;
    int j = lane & 15;
    int start = g_off[v], end = g_off[v + 1];
    float sum = 0.f;
    int e = start + half;
    for (; e + 6 < end; e += 8) {
        int s0 = g_src[e], s1 = g_src[e + 2], s2 = g_src[e + 4], s3 = g_src[e + 6];
        float a0 = g_rs[(size_t)s0 * HD + j];
        float a1 = g_rs[(size_t)s1 * HD + j];
        float a2 = g_rs[(size_t)s2 * HD + j];
        float a3 = g_rs[(size_t)s3 * HD + j];
        sum += (a0 + a1) + (a2 + a3);
    }
    for (; e < end; e += 2) sum += g_rs[(size_t)g_src[e] * HD + j];
    sum += __shfl_xor_sync(0xffffffffu, sum, 16);
    float dv = g_dinv[v];
    float t = (sum + g_rs[(size_t)v * HD + j]) * dv;  // a2 feature j (dup in halves)

    // y = a2 @ W2 + b2 : lane holds class j0=lane, and j1=lane+32 for lane<8
    int j0 = lane;
    int j1 = lane + 32;
    bool has1 = (lane < 8);
    float acc0 = b2[j0];
    float acc1 = has1 ? b2[j1] : 0.f;
#pragma unroll
    for (int k = 0; k < 16; k++) {
        float tk = __shfl_sync(0xffffffffu, t, k);  // lane k holds feature k
        acc0 += tk * W2s[k * NC + j0];
        float w1v = has1 ? W2s[k * NC + j1] : 0.f;
        acc1 += tk * w1v;
    }

    // log_softmax over the 40 classes spread across lanes
    float m = has1 ? fmaxf(acc0, acc1) : acc0;
#pragma unroll
    for (int o = 16; o >= 1; o >>= 1)
        m = fmaxf(m, __shfl_xor_sync(0xffffffffu, m, o));
    float e0 = __expf(acc0 - m);
    float e1 = has1 ? __expf(acc1 - m) : 0.f;
    float s = e0 + e1;
#pragma unroll
    for (int o = 16; o >= 1; o >>= 1)
        s += __shfl_xor_sync(0xffffffffu, s, o);
    float lse = __logf(s);
    out[(size_t)v * NC + j0] = acc0 - m - lse;
    if (has1) out[(size_t)v * NC + j1] = acc1 - m - lse;
}

// ---------------------------------------------------------------------------
extern "C" void kernel_launch(void* const* d_in, const int* in_sizes, int n_in,
                              void* d_out, int out_size) {
    const float* x  = (const float*)d_in[0];
    const void*  ei = d_in[1];
    const float* W1 = (const float*)d_in[2];
    const float* b1 = (const float*)d_in[3];
    const float* W2 = (const float*)d_in[4];
    const float* b2 = (const float*)d_in[5];
    float* out = (float*)d_out;

    k_detect<<<1, 32>>>((const int*)ei);
    k_zero_deg<<<(NN + 255) / 256, 256>>>();
    k_hist<<<(NE + 255) / 256, 256>>>(ei);
    k_scan1<<<(NN + 1023) / 1024, 1024>>>();
    k_scan2<<<1, 128>>>((NN + 1023) / 1024);
    k_scan3<<<(NN + 255) / 256, 256>>>();
    k_scatter<<<(NE + 255) / 256, 256>>>(ei);
    k_gemm1<<<(NN + 31) / 32, 256>>>(x, W1);
    k_agg1<<<(NN + 7) / 8, 256>>>(b1);
    k_agg2_out<<<(NN + 7) / 8, 256>>>(W2, b2, out);
}

// round 2
// speedup vs baseline: 1.0489x; 1.0489x over previous
#include <cuda_runtime.h>
#include <math.h>

#define NN 100000
#define NE 3200000
#define FIN 512
#define HD 16
#define NC 40

// ---------------- device scratch (static: no runtime alloc) ----------------
__device__ int   g_is64;          // 1 if edge_index is int64, 0 if int32
__device__ int   g_deg[NN];       // in-degree (excl. self loop)
__device__ int   g_off[NN + 1];   // CSR offsets (by dst)
__device__ int   g_cur[NN];       // scatter cursors
__device__ int   g_bsum[128];     // block sums for scan
__device__ int   g_src[NE];       // src node per edge, grouped by dst
__device__ float g_dinv[NN];      // 1/sqrt(deg+1)
__device__ float g_h1s[NN * HD];  // (x@W1) * dinv   (pre-scaled)
__device__ float g_rs[NN * HD];   // relu(A_hat h1 + b1) * dinv

// ---------------- f32x2 packed math helpers ----------------
__device__ __forceinline__ unsigned long long pk2(float lo, float hi) {
    unsigned long long r;
    asm("mov.b64 %0, {%1, %2};" : "=l"(r) : "f"(lo), "f"(hi));
    return r;
}
__device__ __forceinline__ unsigned long long fma2(unsigned long long a,
                                                   unsigned long long b,
                                                   unsigned long long c) {
    unsigned long long d;
    asm("fma.rn.f32x2 %0, %1, %2, %3;" : "=l"(d) : "l"(a), "l"(b), "l"(c));
    return d;
}
__device__ __forceinline__ float2 upk2(unsigned long long p) {
    float2 v;
    asm("mov.b64 {%0, %1}, %2;" : "=f"(v.x), "=f"(v.y) : "l"(p));
    return v;
}

// ---------------- init: zero degrees + dtype detect ----------------
__global__ void k_init(const int* __restrict__ ei32) {
    int i = blockIdx.x * 256 + threadIdx.x;
    if (i < NN) g_deg[i] = 0;
    if (blockIdx.x == 0 && threadIdx.x < 32) {
        // int64 node ids < 2^31 => every odd 32-bit word is 0
        int w = ei32[2 * threadIdx.x + 1];
        unsigned nz = __ballot_sync(0xffffffffu, w != 0);
        if (threadIdx.x == 0) g_is64 = (nz == 0) ? 1 : 0;
    }
}

// 4 edges per thread histogram of dst (col) array.
__global__ void k_hist(const void* __restrict__ ei) {
    int t = blockIdx.x * 256 + threadIdx.x;
    if (t >= NE / 4) return;
    int c0, c1, c2, c3;
    if (g_is64) {
        const longlong2* p = (const longlong2*)((const long long*)ei + NE);
        longlong2 a = p[2 * t];
        longlong2 b = p[2 * t + 1];
        c0 = (int)a.x; c1 = (int)a.y; c2 = (int)b.x; c3 = (int)b.y;
    } else {
        int4 a = ((const int4*)((const int*)ei + NE))[t];
        c0 = a.x; c1 = a.y; c2 = a.z; c3 = a.w;
    }
    atomicAdd(&g_deg[c0], 1);
    atomicAdd(&g_deg[c1], 1);
    atomicAdd(&g_deg[c2], 1);
    atomicAdd(&g_deg[c3], 1);
}

// Per-1024-block inclusive scan of degrees -> g_off[i+1] (partial), block sums.
__global__ void k_scan1() {
    int i = blockIdx.x * 1024 + threadIdx.x;
    int val = (i < NN) ? g_deg[i] : 0;
    int lane = threadIdx.x & 31, wid = threadIdx.x >> 5;
    int x = val;
#pragma unroll
    for (int o = 1; o < 32; o <<= 1) {
        int y = __shfl_up_sync(0xffffffffu, x, o);
        if (lane >= o) x += y;
    }
    __shared__ int wsum[32];
    if (lane == 31) wsum[wid] = x;
    __syncthreads();
    if (wid == 0) {
        int w = wsum[lane];
#pragma unroll
        for (int o = 1; o < 32; o <<= 1) {
            int y = __shfl_up_sync(0xffffffffu, w, o);
            if (lane >= o) w += y;
        }
        wsum[lane] = w;
    }
    __syncthreads();
    int incl = x + (wid > 0 ? wsum[wid - 1] : 0);
    if (i < NN) g_off[i + 1] = incl;
    if (threadIdx.x == 1023) g_bsum[blockIdx.x] = incl;
}

// Scan of block sums (nb <= 128), single block Hillis-Steele.
__global__ void k_scan2(int nb) {
    __shared__ int s[128];
    int t = threadIdx.x;
    s[t] = (t < nb) ? g_bsum[t] : 0;
    __syncthreads();
#pragma unroll
    for (int o = 1; o < 128; o <<= 1) {
        int v = (t >= o) ? s[t - o] : 0;
        __syncthreads();
        s[t] += v;
        __syncthreads();
    }
    g_bsum[t] = s[t];
}

// Finalize offsets, cursors, dinv.
__global__ void k_scan3() {
    int i = blockIdx.x * 256 + threadIdx.x;
    if (i >= NN) return;
    int b = i >> 10;
    int add = b ? g_bsum[b - 1] : 0;
    int incl = g_off[i + 1] + add;
    g_off[i + 1] = incl;
    int d = g_deg[i];
    g_cur[i] = incl - d;
    g_dinv[i] = rsqrtf((float)(d + 1));
    if (i == 0) g_off[0] = 0;
}

// 4 edges per thread scatter (row into CSR slot of col).
__global__ void k_scatter(const void* __restrict__ ei) {
    int t = blockIdx.x * 256 + threadIdx.x;
    if (t >= NE / 4) return;
    int r0, r1, r2, r3, c0, c1, c2, c3;
    if (g_is64) {
        const longlong2* pr = (const longlong2*)((const long long*)ei);
        const longlong2* pc = (const longlong2*)((const long long*)ei + NE);
        longlong2 ra = pr[2 * t], rb = pr[2 * t + 1];
        longlong2 ca = pc[2 * t], cb = pc[2 * t + 1];
        r0 = (int)ra.x; r1 = (int)ra.y; r2 = (int)rb.x; r3 = (int)rb.y;
        c0 = (int)ca.x; c1 = (int)ca.y; c2 = (int)cb.x; c3 = (int)cb.y;
    } else {
        int4 ra = ((const int4*)((const int*)ei))[t];
        int4 ca = ((const int4*)((const int*)ei + NE))[t];
        r0 = ra.x; r1 = ra.y; r2 = ra.z; r3 = ra.w;
        c0 = ca.x; c1 = ca.y; c2 = ca.z; c3 = ca.w;
    }
    g_src[atomicAdd(&g_cur[c0], 1)] = r0;
    g_src[atomicAdd(&g_cur[c1], 1)] = r1;
    g_src[atomicAdd(&g_cur[c2], 1)] = r2;
    g_src[atomicAdd(&g_cur[c3], 1)] = r3;
}

// h1s[v] = (x[v] @ W1) * dinv[v]. Warp = 4 rows, packed f32x2 FMA.
__global__ __launch_bounds__(256) void k_gemm1(const float* __restrict__ x,
                                               const float* __restrict__ W1) {
    // Wp[jp*512 + k] = pack(W1[k][2jp], W1[k][2jp+1])
    __shared__ unsigned long long Wp[8 * FIN];
    int tid = threadIdx.x;
    for (int idx = tid; idx < 8 * FIN; idx += 256) {
        int jp = idx >> 9;
        int k = idx & 511;
        Wp[idx] = pk2(W1[k * HD + 2 * jp], W1[k * HD + 2 * jp + 1]);
    }
    __syncthreads();

    int warp = tid >> 5, lane = tid & 31;
    int row0 = (blockIdx.x * 8 + warp) * 4;
    if (row0 >= NN) return;

    const float4* x4 = (const float4*)x;

    unsigned long long acc[4][8];
#pragma unroll
    for (int r = 0; r < 4; r++)
#pragma unroll
        for (int jp = 0; jp < 8; jp++) acc[r][jp] = 0ull;

#pragma unroll
    for (int i = 0; i < 4; i++) {
        int k4 = i * 32 + lane;
        float4 xv[4];
#pragma unroll
        for (int r = 0; r < 4; r++)
            xv[r] = x4[(size_t)(row0 + r) * 128 + k4];
        int kb = k4 * 4;
#pragma unroll
        for (int c = 0; c < 4; c++) {
            unsigned long long xp[4];
#pragma unroll
            for (int r = 0; r < 4; r++) {
                const float* xf = (const float*)&xv[r];
                xp[r] = pk2(xf[c], xf[c]);
            }
#pragma unroll
            for (int jp = 0; jp < 8; jp++) {
                unsigned long long w = Wp[jp * FIN + kb + c];
#pragma unroll
                for (int r = 0; r < 4; r++)
                    acc[r][jp] = fma2(xp[r], w, acc[r][jp]);
            }
        }
    }

    // unpack to 16 scalars per row
    float af[4][16];
#pragma unroll
    for (int r = 0; r < 4; r++)
#pragma unroll
        for (int jp = 0; jp < 8; jp++) {
            float2 v = upk2(acc[r][jp]);
            af[r][2 * jp] = v.x;
            af[r][2 * jp + 1] = v.y;
        }

    // Cross-lane reduction distributing 16 features across lanes 0..15.
#pragma unroll
    for (int r = 0; r < 4; r++) {
#pragma unroll
        for (int f = 0; f < 16; f++)
            af[r][f] += __shfl_xor_sync(0xffffffffu, af[r][f], 16);
#pragma unroll
        for (int o = 8; o > 0; o >>= 1) {
            bool hi = (lane & o) != 0;
#pragma unroll
            for (int f = 0; f < o; f++) {
                float mine = hi ? af[r][f] : af[r][f + o];
                float got = __shfl_xor_sync(0xffffffffu, mine, o);
                float keep = hi ? af[r][f + o] : af[r][f];
                af[r][f] = keep + got;
            }
        }
    }
    if (lane < 16) {
#pragma unroll
        for (int r = 0; r < 4; r++) {
            float dv = g_dinv[row0 + r];
            g_h1s[(size_t)(row0 + r) * HD + lane] = af[r][0] * dv;
        }
    }
}

// Aggregation 1: rs[v] = relu((sum_in h1s + h1s[v])*dinv[v] + b1) * dinv[v]
// Lane layout: slot = lane>>2 (8 edges in flight), fq = lane&3 (float4 chunk).
__global__ __launch_bounds__(256) void k_agg1(const float* __restrict__ b1) {
    int warp = (blockIdx.x * 256 + threadIdx.x) >> 5;
    if (warp >= NN) return;
    int v = warp;
    int lane = threadIdx.x & 31;
    int slot = lane >> 2;
    int fq = lane & 3;
    const float4* h4 = (const float4*)g_h1s;
    int start = g_off[v], end = g_off[v + 1];
    float4 s = make_float4(0.f, 0.f, 0.f, 0.f);
    for (int e = start + slot; e < end; e += 8) {
        int src = g_src[e];
        float4 hv = h4[(size_t)src * 4 + fq];
        s.x += hv.x; s.y += hv.y; s.z += hv.z; s.w += hv.w;
    }
#pragma unroll
    for (int o = 4; o <= 16; o <<= 1) {
        s.x += __shfl_xor_sync(0xffffffffu, s.x, o);
        s.y += __shfl_xor_sync(0xffffffffu, s.y, o);
        s.z += __shfl_xor_sync(0xffffffffu, s.z, o);
        s.w += __shfl_xor_sync(0xffffffffu, s.w, o);
    }
    float4 self = h4[(size_t)v * 4 + fq];
    float dv = g_dinv[v];
    float4 bb = ((const float4*)b1)[fq];
    float4 r;
    r.x = fmaxf((s.x + self.x) * dv + bb.x, 0.f) * dv;
    r.y = fmaxf((s.y + self.y) * dv + bb.y, 0.f) * dv;
    r.z = fmaxf((s.z + self.z) * dv + bb.z, 0.f) * dv;
    r.w = fmaxf((s.w + self.w) * dv + bb.w, 0.f) * dv;
    if (slot == 0) ((float4*)g_rs)[(size_t)v * 4 + fq] = r;
}

// Aggregation 2 fused with 16->40 GEMM + log_softmax.
__global__ __launch_bounds__(256) void k_agg2_out(const float* __restrict__ W2,
                                                 const float* __restrict__ b2,
                                                 float* __restrict__ out) {
    __shared__ float W2s[HD * NC];
    int tid = threadIdx.x;
    for (int idx = tid; idx < HD * NC; idx += 256) W2s[idx] = W2[idx];
    __syncthreads();

    int warp = (blockIdx.x * 256 + tid) >> 5;
    if (warp >= NN) return;
    int v = warp;
    int lane = tid & 31;
    int slot = lane >> 2;
    int fq = lane & 3;
    const float4* r4 = (const float4*)g_rs;
    int start = g_off[v], end = g_off[v + 1];
    float4 s = make_float4(0.f, 0.f, 0.f, 0.f);
    for (int e = start + slot; e < end; e += 8) {
        int src = g_src[e];
        float4 hv = r4[(size_t)src * 4 + fq];
        s.x += hv.x; s.y += hv.y; s.z += hv.z; s.w += hv.w;
    }
#pragma unroll
    for (int o = 4; o <= 16; o <<= 1) {
        s.x += __shfl_xor_sync(0xffffffffu, s.x, o);
        s.y += __shfl_xor_sync(0xffffffffu, s.y, o);
        s.z += __shfl_xor_sync(0xffffffffu, s.z, o);
        s.w += __shfl_xor_sync(0xffffffffu, s.w, o);
    }
    float4 self = r4[(size_t)v * 4 + fq];
    float dv = g_dinv[v];
    float4 t4;
    t4.x = (s.x + self.x) * dv;
    t4.y = (s.y + self.y) * dv;
    t4.z = (s.z + self.z) * dv;
    t4.w = (s.w + self.w) * dv;

    // broadcast full 16-vector to every lane (lane q holds quad q for q<4)
    float f[16];
#pragma unroll
    for (int q = 0; q < 4; q++) {
        f[4 * q + 0] = __shfl_sync(0xffffffffu, t4.x, q);
        f[4 * q + 1] = __shfl_sync(0xffffffffu, t4.y, q);
        f[4 * q + 2] = __shfl_sync(0xffffffffu, t4.z, q);
        f[4 * q + 3] = __shfl_sync(0xffffffffu, t4.w, q);
    }

    // y = a2 @ W2 + b2 : lane holds class j0=lane, and j1=lane+32 for lane<8
    int j0 = lane;
    int j1 = lane + 32;
    bool has1 = (lane < 8);
    float acc0 = b2[j0];
    float acc1 = has1 ? b2[j1] : 0.f;
#pragma unroll
    for (int k = 0; k < 16; k++) {
        acc0 += f[k] * W2s[k * NC + j0];
        float w1v = has1 ? W2s[k * NC + j1] : 0.f;
        acc1 += f[k] * w1v;
    }

    // log_softmax over 40 classes spread across lanes
    float m = has1 ? fmaxf(acc0, acc1) : acc0;
#pragma unroll
    for (int o = 16; o >= 1; o >>= 1)
        m = fmaxf(m, __shfl_xor_sync(0xffffffffu, m, o));
    float e0 = __expf(acc0 - m);
    float e1 = has1 ? __expf(acc1 - m) : 0.f;
    float sm = e0 + e1;
#pragma unroll
    for (int o = 16; o >= 1; o >>= 1)
        sm += __shfl_xor_sync(0xffffffffu, sm, o);
    float lse = __logf(sm);
    out[(size_t)v * NC + j0] = acc0 - m - lse;
    if (has1) out[(size_t)v * NC + j1] = acc1 - m - lse;
}

// ---------------------------------------------------------------------------
extern "C" void kernel_launch(void* const* d_in, const int* in_sizes, int n_in,
                              void* d_out, int out_size) {
    const float* x  = (const float*)d_in[0];
    const void*  ei = d_in[1];
    const float* W1 = (const float*)d_in[2];
    const float* b1 = (const float*)d_in[3];
    const float* W2 = (const float*)d_in[4];
    const float* b2 = (const float*)d_in[5];
    float* out = (float*)d_out;

    k_init<<<(NN + 255) / 256, 256>>>((const int*)ei);
    k_hist<<<(NE / 4 + 255) / 256, 256>>>(ei);
    k_scan1<<<(NN + 1023) / 1024, 1024>>>();
    k_scan2<<<1, 128>>>((NN + 1023) / 1024);
    k_scan3<<<(NN + 255) / 256, 256>>>();
    k_scatter<<<(NE / 4 + 255) / 256, 256>>>(ei);
    k_gemm1<<<(NN + 31) / 32, 256>>>(x, W1);
    k_agg1<<<(NN + 7) / 8, 256>>>(b1);
    k_agg2_out<<<(NN + 7) / 8, 256>>>(W2, b2, out);
}

// round 3
// speedup vs baseline: 1.0635x; 1.0138x over previous
#include <cuda_runtime.h>
#include <math.h>

#define NN 100000
#define NE 3200000
#define FIN 512
#define HD 16
#define NC 40

// ---------------- device scratch (static: no runtime alloc) ----------------
__device__ int   g_is64;          // 1 if edge_index is int64, 0 if int32
__device__ int   g_deg[NN];       // in-degree (excl. self loop)
__device__ int   g_off[NN + 1];   // CSR offsets (by dst)
__device__ int   g_cur[NN];       // scatter cursors
__device__ int   g_bsum[128];     // block sums for scan
__device__ int   g_ctr;           // scan arrival counter
__device__ int   g_flag;          // scan middle-phase done flag
__device__ int   g_src[NE];       // src node per edge, grouped by dst
__device__ float g_dinv[NN];      // 1/sqrt(deg+1)
__device__ float g_h1s[NN * HD];  // (x@W1) * dinv   (pre-scaled)
__device__ float g_rs[NN * HD];   // relu(A_hat h1 + b1) * dinv

// ---------------- f32x2 packed math helpers ----------------
__device__ __forceinline__ unsigned long long pk2(float lo, float hi) {
    unsigned long long r;
    asm("mov.b64 %0, {%1, %2};" : "=l"(r) : "f"(lo), "f"(hi));
    return r;
}
__device__ __forceinline__ unsigned long long fma2(unsigned long long a,
                                                   unsigned long long b,
                                                   unsigned long long c) {
    unsigned long long d;
    asm("fma.rn.f32x2 %0, %1, %2, %3;" : "=l"(d) : "l"(a), "l"(b), "l"(c));
    return d;
}
__device__ __forceinline__ float2 upk2(unsigned long long p) {
    float2 v;
    asm("mov.b64 {%0, %1}, %2;" : "=f"(v.x), "=f"(v.y) : "l"(p));
    return v;
}

// ---------------- init: zero degrees + dtype detect + scan-state reset -----
__global__ void k_init(const int* __restrict__ ei32) {
    int i = blockIdx.x * 256 + threadIdx.x;
    if (i < NN) g_deg[i] = 0;
    if (blockIdx.x == 0 && threadIdx.x < 32) {
        // int64 node ids < 2^31 => every odd 32-bit word is 0
        int w = ei32[2 * threadIdx.x + 1];
        unsigned nz = __ballot_sync(0xffffffffu, w != 0);
        if (threadIdx.x == 0) {
            g_is64 = (nz == 0) ? 1 : 0;
            g_ctr = 0;
            g_flag = 0;
        }
    }
}

// 4 edges per thread histogram of dst (col) array.
__global__ void k_hist(const void* __restrict__ ei) {
    int t = blockIdx.x * 256 + threadIdx.x;
    if (t >= NE / 4) return;
    int c0, c1, c2, c3;
    if (g_is64) {
        const longlong2* p = (const longlong2*)((const long long*)ei + NE);
        longlong2 a = p[2 * t];
        longlong2 b = p[2 * t + 1];
        c0 = (int)a.x; c1 = (int)a.y; c2 = (int)b.x; c3 = (int)b.y;
    } else {
        int4 a = ((const int4*)((const int*)ei + NE))[t];
        c0 = a.x; c1 = a.y; c2 = a.z; c3 = a.w;
    }
    atomicAdd(&g_deg[c0], 1);
    atomicAdd(&g_deg[c1], 1);
    atomicAdd(&g_deg[c2], 1);
    atomicAdd(&g_deg[c3], 1);
}

// Single-kernel full scan: local block scan, last-arriving block scans block
// sums, everyone finalizes offsets / cursors / dinv. grid = 98 blocks x 1024
// (single wave on 148 SMs -> spin-wait is safe).
__global__ __launch_bounds__(1024) void k_scan_all() {
    int b = blockIdx.x;
    int i = b * 1024 + threadIdx.x;
    int val = (i < NN) ? g_deg[i] : 0;
    int lane = threadIdx.x & 31, wid = threadIdx.x >> 5;
    int x = val;
#pragma unroll
    for (int o = 1; o < 32; o <<= 1) {
        int y = __shfl_up_sync(0xffffffffu, x, o);
        if (lane >= o) x += y;
    }
    __shared__ int wsum[32];
    __shared__ int amLast;
    if (lane == 31) wsum[wid] = x;
    __syncthreads();
    if (wid == 0) {
        int w = wsum[lane];
#pragma unroll
        for (int o = 1; o < 32; o <<= 1) {
            int y = __shfl_up_sync(0xffffffffu, w, o);
            if (lane >= o) w += y;
        }
        wsum[lane] = w;
    }
    __syncthreads();
    int incl = x + (wid > 0 ? wsum[wid - 1] : 0);
    if (threadIdx.x == 1023) g_bsum[b] = incl;  // block total
    __syncthreads();
    if (threadIdx.x == 0) {
        __threadfence();  // cumulative: orders t1023's bsum write (hb via bar)
        amLast = (atomicAdd(&g_ctr, 1) == gridDim.x - 1);
    }
    __syncthreads();
    if (amLast) {
        if (threadIdx.x == 0) __threadfence();  // see all blocks' bsum writes
        __syncthreads();
        if (threadIdx.x < 32) {
            int nb = gridDim.x;
            int base = threadIdx.x * 4;
            int v0 = (base + 0 < nb) ? g_bsum[base + 0] : 0;
            int v1 = (base + 1 < nb) ? g_bsum[base + 1] : 0;
            int v2 = (base + 2 < nb) ? g_bsum[base + 2] : 0;
            int v3 = (base + 3 < nb) ? g_bsum[base + 3] : 0;
            int s0 = v0, s1 = s0 + v1, s2 = s1 + v2, s3 = s2 + v3;
            int tot = s3;
            int xs = tot;
#pragma unroll
            for (int o = 1; o < 32; o <<= 1) {
                int y = __shfl_up_sync(0xffffffffu, xs, o);
                if (lane >= o) xs += y;
            }
            int excl = xs - tot;
            g_bsum[base + 0] = s0 + excl;
            g_bsum[base + 1] = s1 + excl;
            g_bsum[base + 2] = s2 + excl;
            g_bsum[base + 3] = s3 + excl;
            __syncwarp();
            if (threadIdx.x == 0) {
                int one = 1;
                asm volatile("st.release.gpu.b32 [%0], %1;" ::"l"(&g_flag),
                             "r"(one) : "memory");
            }
        }
    }
    if (threadIdx.x == 0) {
        int f;
        do {
            asm volatile("ld.acquire.gpu.b32 %0, [%1];" : "=r"(f)
                         : "l"(&g_flag) : "memory");
        } while (f == 0);
    }
    __syncthreads();
    int add = (b > 0) ? g_bsum[b - 1] : 0;
    int fin = incl + add;
    if (i < NN) {
        g_off[i + 1] = fin;
        g_cur[i] = fin - val;
        g_dinv[i] = rsqrtf((float)(val + 1));
    }
    if (i == 0) g_off[0] = 0;
}

// h1s[v] = (x[v] @ W1) * dinv[v]. Warp = 4 rows, packed f32x2 FMA.
__global__ __launch_bounds__(256) void k_gemm1(const float* __restrict__ x,
                                               const float* __restrict__ W1) {
    // Wp[jp*512 + k] = pack(W1[k][2jp], W1[k][2jp+1])
    __shared__ unsigned long long Wp[8 * FIN];
    int tid = threadIdx.x;
    for (int idx = tid; idx < 8 * FIN; idx += 256) {
        int jp = idx >> 9;
        int k = idx & 511;
        Wp[idx] = pk2(W1[k * HD + 2 * jp], W1[k * HD + 2 * jp + 1]);
    }
    __syncthreads();

    int warp = tid >> 5, lane = tid & 31;
    int row0 = (blockIdx.x * 8 + warp) * 4;
    if (row0 >= NN) return;

    const float4* x4 = (const float4*)x;

    unsigned long long acc[4][8];
#pragma unroll
    for (int r = 0; r < 4; r++)
#pragma unroll
        for (int jp = 0; jp < 8; jp++) acc[r][jp] = 0ull;

#pragma unroll
    for (int i = 0; i < 4; i++) {
        int k4 = i * 32 + lane;
        float4 xv[4];
#pragma unroll
        for (int r = 0; r < 4; r++)
            xv[r] = x4[(size_t)(row0 + r) * 128 + k4];
        int kb = k4 * 4;
#pragma unroll
        for (int c = 0; c < 4; c++) {
            unsigned long long xp[4];
#pragma unroll
            for (int r = 0; r < 4; r++) {
                const float* xf = (const float*)&xv[r];
                xp[r] = pk2(xf[c], xf[c]);
            }
#pragma unroll
            for (int jp = 0; jp < 8; jp++) {
                unsigned long long w = Wp[jp * FIN + kb + c];
#pragma unroll
                for (int r = 0; r < 4; r++)
                    acc[r][jp] = fma2(xp[r], w, acc[r][jp]);
            }
        }
    }

    // unpack to 16 scalars per row
    float af[4][16];
#pragma unroll
    for (int r = 0; r < 4; r++)
#pragma unroll
        for (int jp = 0; jp < 8; jp++) {
            float2 v = upk2(acc[r][jp]);
            af[r][2 * jp] = v.x;
            af[r][2 * jp + 1] = v.y;
        }

    // Cross-lane reduction distributing 16 features across lanes 0..15.
#pragma unroll
    for (int r = 0; r < 4; r++) {
#pragma unroll
        for (int f = 0; f < 16; f++)
            af[r][f] += __shfl_xor_sync(0xffffffffu, af[r][f], 16);
#pragma unroll
        for (int o = 8; o > 0; o >>= 1) {
            bool hi = (lane & o) != 0;
#pragma unroll
            for (int f = 0; f < o; f++) {
                float mine = hi ? af[r][f] : af[r][f + o];
                float got = __shfl_xor_sync(0xffffffffu, mine, o);
                float keep = hi ? af[r][f + o] : af[r][f];
                af[r][f] = keep + got;
            }
        }
    }
    if (lane < 16) {
#pragma unroll
        for (int r = 0; r < 4; r++) {
            float dv = g_dinv[row0 + r];
            g_h1s[(size_t)(row0 + r) * HD + lane] = af[r][0] * dv;
        }
    }
}

// 4 edges per thread scatter (row into CSR slot of col).
__global__ void k_scatter(const void* __restrict__ ei) {
    int t = blockIdx.x * 256 + threadIdx.x;
    if (t >= NE / 4) return;
    int r0, r1, r2, r3, c0, c1, c2, c3;
    if (g_is64) {
        const longlong2* pr = (const longlong2*)((const long long*)ei);
        const longlong2* pc = (const longlong2*)((const long long*)ei + NE);
        longlong2 ra = pr[2 * t], rb = pr[2 * t + 1];
        longlong2 ca = pc[2 * t], cb = pc[2 * t + 1];
        r0 = (int)ra.x; r1 = (int)ra.y; r2 = (int)rb.x; r3 = (int)rb.y;
        c0 = (int)ca.x; c1 = (int)ca.y; c2 = (int)cb.x; c3 = (int)cb.y;
    } else {
        int4 ra = ((const int4*)((const int*)ei))[t];
        int4 ca = ((const int4*)((const int*)ei + NE))[t];
        r0 = ra.x; r1 = ra.y; r2 = ra.z; r3 = ra.w;
        c0 = ca.x; c1 = ca.y; c2 = ca.z; c3 = ca.w;
    }
    g_src[atomicAdd(&g_cur[c0], 1)] = r0;
    g_src[atomicAdd(&g_cur[c1], 1)] = r1;
    g_src[atomicAdd(&g_cur[c2], 1)] = r2;
    g_src[atomicAdd(&g_cur[c3], 1)] = r3;
}

// Aggregation 1: rs[v] = relu((sum_in h1s + h1s[v])*dinv[v] + b1) * dinv[v]
// Lane layout: slot = lane>>2 (8 edge slots), fq = lane&3 (float4 chunk).
// Dual accumulators -> 2 independent gather chains in flight per lane.
__global__ __launch_bounds__(256) void k_agg1(const float* __restrict__ b1) {
    int warp = (blockIdx.x * 256 + threadIdx.x) >> 5;
    if (warp >= NN) return;
    int v = warp;
    int lane = threadIdx.x & 31;
    int slot = lane >> 2;
    int fq = lane & 3;
    const float4* h4 = (const float4*)g_h1s;
    int start = g_off[v], end = g_off[v + 1];
    float4 s = make_float4(0.f, 0.f, 0.f, 0.f);
    float4 s2 = make_float4(0.f, 0.f, 0.f, 0.f);
    int e = start + slot;
    for (; e + 8 < end; e += 16) {
        int sa = g_src[e];
        int sb = g_src[e + 8];
        float4 ha = h4[(size_t)sa * 4 + fq];
        float4 hb = h4[(size_t)sb * 4 + fq];
        s.x += ha.x; s.y += ha.y; s.z += ha.z; s.w += ha.w;
        s2.x += hb.x; s2.y += hb.y; s2.z += hb.z; s2.w += hb.w;
    }
    if (e < end) {
        float4 ha = h4[(size_t)g_src[e] * 4 + fq];
        s.x += ha.x; s.y += ha.y; s.z += ha.z; s.w += ha.w;
    }
    s.x += s2.x; s.y += s2.y; s.z += s2.z; s.w += s2.w;
#pragma unroll
    for (int o = 4; o <= 16; o <<= 1) {
        s.x += __shfl_xor_sync(0xffffffffu, s.x, o);
        s.y += __shfl_xor_sync(0xffffffffu, s.y, o);
        s.z += __shfl_xor_sync(0xffffffffu, s.z, o);
        s.w += __shfl_xor_sync(0xffffffffu, s.w, o);
    }
    float4 self = h4[(size_t)v * 4 + fq];
    float dv = g_dinv[v];
    float4 bb = ((const float4*)b1)[fq];
    float4 r;
    r.x = fmaxf((s.x + self.x) * dv + bb.x, 0.f) * dv;
    r.y = fmaxf((s.y + self.y) * dv + bb.y, 0.f) * dv;
    r.z = fmaxf((s.z + self.z) * dv + bb.z, 0.f) * dv;
    r.w = fmaxf((s.w + self.w) * dv + bb.w, 0.f) * dv;
    if (slot == 0) ((float4*)g_rs)[(size_t)v * 4 + fq] = r;
}

// Aggregation 2 fused with 16->40 GEMM + log_softmax.
__global__ __launch_bounds__(256) void k_agg2_out(const float* __restrict__ W2,
                                                 const float* __restrict__ b2,
                                                 float* __restrict__ out) {
    __shared__ float W2s[HD * NC];
    int tid = threadIdx.x;
    for (int idx = tid; idx < HD * NC; idx += 256) W2s[idx] = W2[idx];
    __syncthreads();

    int warp = (blockIdx.x * 256 + tid) >> 5;
    if (warp >= NN) return;
    int v = warp;
    int lane = tid & 31;
    int slot = lane >> 2;
    int fq = lane & 3;
    const float4* r4 = (const float4*)g_rs;
    int start = g_off[v], end = g_off[v + 1];
    float4 s = make_float4(0.f, 0.f, 0.f, 0.f);
    float4 s2 = make_float4(0.f, 0.f, 0.f, 0.f);
    int e = start + slot;
    for (; e + 8 < end; e += 16) {
        int sa = g_src[e];
        int sb = g_src[e + 8];
        float4 ha = r4[(size_t)sa * 4 + fq];
        float4 hb = r4[(size_t)sb * 4 + fq];
        s.x += ha.x; s.y += ha.y; s.z += ha.z; s.w += ha.w;
        s2.x += hb.x; s2.y += hb.y; s2.z += hb.z; s2.w += hb.w;
    }
    if (e < end) {
        float4 ha = r4[(size_t)g_src[e] * 4 + fq];
        s.x += ha.x; s.y += ha.y; s.z += ha.z; s.w += ha.w;
    }
    s.x += s2.x; s.y += s2.y; s.z += s2.z; s.w += s2.w;
#pragma unroll
    for (int o = 4; o <= 16; o <<= 1) {
        s.x += __shfl_xor_sync(0xffffffffu, s.x, o);
        s.y += __shfl_xor_sync(0xffffffffu, s.y, o);
        s.z += __shfl_xor_sync(0xffffffffu, s.z, o);
        s.w += __shfl_xor_sync(0xffffffffu, s.w, o);
    }
    float4 self = r4[(size_t)v * 4 + fq];
    float dv = g_dinv[v];
    float4 t4;
    t4.x = (s.x + self.x) * dv;
    t4.y = (s.y + self.y) * dv;
    t4.z = (s.z + self.z) * dv;
    t4.w = (s.w + self.w) * dv;

    // broadcast full 16-vector to every lane (lane q holds quad q for q<4)
    float f[16];
#pragma unroll
    for (int q = 0; q < 4; q++) {
        f[4 * q + 0] = __shfl_sync(0xffffffffu, t4.x, q);
        f[4 * q + 1] = __shfl_sync(0xffffffffu, t4.y, q);
        f[4 * q + 2] = __shfl_sync(0xffffffffu, t4.z, q);
        f[4 * q + 3] = __shfl_sync(0xffffffffu, t4.w, q);
    }

    // y = a2 @ W2 + b2 : lane holds class j0=lane, and j1=lane+32 for lane<8
    int j0 = lane;
    int j1 = lane + 32;
    bool has1 = (lane < 8);
    float acc0 = b2[j0];
    float acc1 = has1 ? b2[j1] : 0.f;
#pragma unroll
    for (int k = 0; k < 16; k++) {
        acc0 += f[k] * W2s[k * NC + j0];
        float w1v = has1 ? W2s[k * NC + j1] : 0.f;
        acc1 += f[k] * w1v;
    }

    // log_softmax over 40 classes spread across lanes
    float m = has1 ? fmaxf(acc0, acc1) : acc0;
#pragma unroll
    for (int o = 16; o >= 1; o >>= 1)
        m = fmaxf(m, __shfl_xor_sync(0xffffffffu, m, o));
    float e0 = __expf(acc0 - m);
    float e1 = has1 ? __expf(acc1 - m) : 0.f;
    float sm = e0 + e1;
#pragma unroll
    for (int o = 16; o >= 1; o >>= 1)
        sm += __shfl_xor_sync(0xffffffffu, sm, o);
    float lse = __logf(sm);
    out[(size_t)v * NC + j0] = acc0 - m - lse;
    if (has1) out[(size_t)v * NC + j1] = acc1 - m - lse;
}

// ---------------------------------------------------------------------------
extern "C" void kernel_launch(void* const* d_in, const int* in_sizes, int n_in,
                              void* d_out, int out_size) {
    const float* x  = (const float*)d_in[0];
    const void*  ei = d_in[1];
    const float* W1 = (const float*)d_in[2];
    const float* b1 = (const float*)d_in[3];
    const float* W2 = (const float*)d_in[4];
    const float* b2 = (const float*)d_in[5];
    float* out = (float*)d_out;

    k_init<<<(NN + 255) / 256, 256>>>((const int*)ei);           // #0
    k_hist<<<(NE / 4 + 255) / 256, 256>>>(ei);                   // #1
    k_scan_all<<<(NN + 1023) / 1024, 1024>>>();                  // #2
    k_gemm1<<<(NN + 31) / 32, 256>>>(x, W1);                     // #3 (profiled)
    k_scatter<<<(NE / 4 + 255) / 256, 256>>>(ei);                // #4
    k_agg1<<<(NN + 7) / 8, 256>>>(b1);                           // #5
    k_agg2_out<<<(NN + 7) / 8, 256>>>(W2, b2, out);              // #6
}

// round 4
// speedup vs baseline: 1.0862x; 1.0214x over previous
#include <cuda_runtime.h>
#include <math.h>

#define NN 100000
#define NE 3200000
#define FIN 512
#define HD 16
#define NC 40

// ---------------- device scratch (static: no runtime alloc) ----------------
__device__ int   g_is64;          // 1 if edge_index is int64, 0 if int32
__device__ int   g_deg[NN];       // in-degree (zeroed by scan tail each run)
__device__ int   g_off[NN + 1];   // CSR offsets (by dst)
__device__ int   g_cur[NN];       // scatter cursors
__device__ int   g_bsum[128];     // block sums for scan
__device__ int   g_ctr;           // scan arrival counter
__device__ int   g_flag;          // scan middle-phase done flag
__device__ int   g_src[NE];       // src node per edge, grouped by dst
__device__ float g_dinv[NN];      // 1/sqrt(deg+1)
__device__ float g_h1s[NN * HD];  // (x@W1) * dinv   (pre-scaled)
__device__ float g_rs[NN * HD];   // relu(A_hat h1 + b1) * dinv

// ---------------- f32x2 packed math helpers ----------------
__device__ __forceinline__ unsigned long long pk2(float lo, float hi) {
    unsigned long long r;
    asm("mov.b64 %0, {%1, %2};" : "=l"(r) : "f"(lo), "f"(hi));
    return r;
}
__device__ __forceinline__ unsigned long long fma2(unsigned long long a,
                                                   unsigned long long b,
                                                   unsigned long long c) {
    unsigned long long d;
    asm("fma.rn.f32x2 %0, %1, %2, %3;" : "=l"(d) : "l"(a), "l"(b), "l"(c));
    return d;
}
__device__ __forceinline__ float2 upk2(unsigned long long p) {
    float2 v;
    asm("mov.b64 {%0, %1}, %2;" : "=f"(v.x), "=f"(v.y) : "l"(p));
    return v;
}

// ---------------- init: dtype detect + scan-state reset (1 block) ----------
__global__ void k_init(const int* __restrict__ ei32) {
    // int64 node ids < 2^31 => every odd 32-bit word is 0
    int w = ei32[2 * threadIdx.x + 1];
    unsigned nz = __ballot_sync(0xffffffffu, w != 0);
    if (threadIdx.x == 0) {
        g_is64 = (nz == 0) ? 1 : 0;
        g_ctr = 0;
        g_flag = 0;
    }
}

// 4 edges per thread histogram of dst (col) array.
__global__ void k_hist(const void* __restrict__ ei) {
    int t = blockIdx.x * 256 + threadIdx.x;
    if (t >= NE / 4) return;
    int c0, c1, c2, c3;
    if (g_is64) {
        const longlong2* p = (const longlong2*)((const long long*)ei + NE);
        longlong2 a = p[2 * t];
        longlong2 b = p[2 * t + 1];
        c0 = (int)a.x; c1 = (int)a.y; c2 = (int)b.x; c3 = (int)b.y;
    } else {
        int4 a = ((const int4*)((const int*)ei + NE))[t];
        c0 = a.x; c1 = a.y; c2 = a.z; c3 = a.w;
    }
    atomicAdd(&g_deg[c0], 1);
    atomicAdd(&g_deg[c1], 1);
    atomicAdd(&g_deg[c2], 1);
    atomicAdd(&g_deg[c3], 1);
}

// Single-kernel full scan: local block scan, last-arriving block scans block
// sums, everyone finalizes offsets / cursors / dinv, then re-zeros g_deg so
// the next replay's histogram starts clean. grid = 98 blocks (single wave).
__global__ __launch_bounds__(1024) void k_scan_all() {
    int b = blockIdx.x;
    int i = b * 1024 + threadIdx.x;
    int val = (i < NN) ? g_deg[i] : 0;
    int lane = threadIdx.x & 31, wid = threadIdx.x >> 5;
    int x = val;
#pragma unroll
    for (int o = 1; o < 32; o <<= 1) {
        int y = __shfl_up_sync(0xffffffffu, x, o);
        if (lane >= o) x += y;
    }
    __shared__ int wsum[32];
    __shared__ int amLast;
    if (lane == 31) wsum[wid] = x;
    __syncthreads();
    if (wid == 0) {
        int w = wsum[lane];
#pragma unroll
        for (int o = 1; o < 32; o <<= 1) {
            int y = __shfl_up_sync(0xffffffffu, w, o);
            if (lane >= o) w += y;
        }
        wsum[lane] = w;
    }
    __syncthreads();
    int incl = x + (wid > 0 ? wsum[wid - 1] : 0);
    if (threadIdx.x == 1023) g_bsum[b] = incl;  // block total
    __syncthreads();
    if (threadIdx.x == 0) {
        __threadfence();
        amLast = (atomicAdd(&g_ctr, 1) == gridDim.x - 1);
    }
    __syncthreads();
    if (amLast) {
        if (threadIdx.x == 0) __threadfence();
        __syncthreads();
        if (threadIdx.x < 32) {
            int nb = gridDim.x;
            int base = threadIdx.x * 4;
            int v0 = (base + 0 < nb) ? g_bsum[base + 0] : 0;
            int v1 = (base + 1 < nb) ? g_bsum[base + 1] : 0;
            int v2 = (base + 2 < nb) ? g_bsum[base + 2] : 0;
            int v3 = (base + 3 < nb) ? g_bsum[base + 3] : 0;
            int s0 = v0, s1 = s0 + v1, s2 = s1 + v2, s3 = s2 + v3;
            int tot = s3;
            int xs = tot;
#pragma unroll
            for (int o = 1; o < 32; o <<= 1) {
                int y = __shfl_up_sync(0xffffffffu, xs, o);
                if (lane >= o) xs += y;
            }
            int excl = xs - tot;
            g_bsum[base + 0] = s0 + excl;
            g_bsum[base + 1] = s1 + excl;
            g_bsum[base + 2] = s2 + excl;
            g_bsum[base + 3] = s3 + excl;
            __syncwarp();
            if (threadIdx.x == 0) {
                int one = 1;
                asm volatile("st.release.gpu.b32 [%0], %1;" ::"l"(&g_flag),
                             "r"(one) : "memory");
            }
        }
    }
    if (threadIdx.x == 0) {
        int f;
        do {
            asm volatile("ld.acquire.gpu.b32 %0, [%1];" : "=r"(f)
                         : "l"(&g_flag) : "memory");
        } while (f == 0);
    }
    __syncthreads();
    int add = (b > 0) ? g_bsum[b - 1] : 0;
    int fin = incl + add;
    if (i < NN) {
        g_off[i + 1] = fin;
        g_cur[i] = fin - val;
        g_dinv[i] = rsqrtf((float)(val + 1));
        g_deg[i] = 0;  // restore invariant for the next replay
    }
    if (i == 0) g_off[0] = 0;
}

// h1s[v] = (x[v] @ W1) * dinv[v]. Warp = 4 rows, packed f32x2 FMA.
// W staged as Wq[(jp*4+c)][k4] so LDS.64 is lane-contiguous (conflict-free).
__global__ __launch_bounds__(256) void k_gemm1(const float* __restrict__ x,
                                               const float* __restrict__ W1) {
    __shared__ unsigned long long Wq[32 * 128];  // [(jp,c)][k4]
    int tid = threadIdx.x;
    for (int idx = tid; idx < 32 * 128; idx += 256) {
        int jpc = idx >> 7;   // jp*4 + c
        int k4 = idx & 127;
        int jp = jpc >> 2, c = jpc & 3;
        int k = k4 * 4 + c;
        Wq[idx] = pk2(W1[k * HD + 2 * jp], W1[k * HD + 2 * jp + 1]);
    }
    __syncthreads();

    int warp = tid >> 5, lane = tid & 31;
    int row0 = (blockIdx.x * 8 + warp) * 4;
    if (row0 >= NN) return;

    const float4* x4 = (const float4*)x;

    unsigned long long acc[4][8];
#pragma unroll
    for (int r = 0; r < 4; r++)
#pragma unroll
        for (int jp = 0; jp < 8; jp++) acc[r][jp] = 0ull;

#pragma unroll
    for (int i = 0; i < 4; i++) {
        int k4 = i * 32 + lane;
        float4 xv[4];
#pragma unroll
        for (int r = 0; r < 4; r++)
            xv[r] = x4[(size_t)(row0 + r) * 128 + k4];
#pragma unroll
        for (int c = 0; c < 4; c++) {
            unsigned long long xp[4];
#pragma unroll
            for (int r = 0; r < 4; r++) {
                const float* xf = (const float*)&xv[r];
                xp[r] = pk2(xf[c], xf[c]);
            }
#pragma unroll
            for (int jp = 0; jp < 8; jp++) {
                unsigned long long w = Wq[(jp * 4 + c) * 128 + k4];
#pragma unroll
                for (int r = 0; r < 4; r++)
                    acc[r][jp] = fma2(xp[r], w, acc[r][jp]);
            }
        }
    }

    // unpack to 16 scalars per row
    float af[4][16];
#pragma unroll
    for (int r = 0; r < 4; r++)
#pragma unroll
        for (int jp = 0; jp < 8; jp++) {
            float2 v = upk2(acc[r][jp]);
            af[r][2 * jp] = v.x;
            af[r][2 * jp + 1] = v.y;
        }

    // Cross-lane reduction distributing 16 features across lanes 0..15.
#pragma unroll
    for (int r = 0; r < 4; r++) {
#pragma unroll
        for (int f = 0; f < 16; f++)
            af[r][f] += __shfl_xor_sync(0xffffffffu, af[r][f], 16);
#pragma unroll
        for (int o = 8; o > 0; o >>= 1) {
            bool hi = (lane & o) != 0;
#pragma unroll
            for (int f = 0; f < o; f++) {
                float mine = hi ? af[r][f] : af[r][f + o];
                float got = __shfl_xor_sync(0xffffffffu, mine, o);
                float keep = hi ? af[r][f + o] : af[r][f];
                af[r][f] = keep + got;
            }
        }
    }
    if (lane < 16) {
#pragma unroll
        for (int r = 0; r < 4; r++) {
            float dv = g_dinv[row0 + r];
            g_h1s[(size_t)(row0 + r) * HD + lane] = af[r][0] * dv;
        }
    }
}

// 4 edges per thread scatter (row into CSR slot of col).
__global__ void k_scatter(const void* __restrict__ ei) {
    int t = blockIdx.x * 256 + threadIdx.x;
    if (t >= NE / 4) return;
    int r0, r1, r2, r3, c0, c1, c2, c3;
    if (g_is64) {
        const longlong2* pr = (const longlong2*)((const long long*)ei);
        const longlong2* pc = (const longlong2*)((const long long*)ei + NE);
        longlong2 ra = pr[2 * t], rb = pr[2 * t + 1];
        longlong2 ca = pc[2 * t], cb = pc[2 * t + 1];
        r0 = (int)ra.x; r1 = (int)ra.y; r2 = (int)rb.x; r3 = (int)rb.y;
        c0 = (int)ca.x; c1 = (int)ca.y; c2 = (int)cb.x; c3 = (int)cb.y;
    } else {
        int4 ra = ((const int4*)((const int*)ei))[t];
        int4 ca = ((const int4*)((const int*)ei + NE))[t];
        r0 = ra.x; r1 = ra.y; r2 = ra.z; r3 = ra.w;
        c0 = ca.x; c1 = ca.y; c2 = ca.z; c3 = ca.w;
    }
    g_src[atomicAdd(&g_cur[c0], 1)] = r0;
    g_src[atomicAdd(&g_cur[c1], 1)] = r1;
    g_src[atomicAdd(&g_cur[c2], 1)] = r2;
    g_src[atomicAdd(&g_cur[c3], 1)] = r3;
}

// Aggregation 1: rs[v] = relu((sum_in h1s + h1s[v])*dinv[v] + b1) * dinv[v]
// Lane layout: slot = lane>>2 (8 edge slots), fq = lane&3 (float4 chunk).
__global__ __launch_bounds__(256) void k_agg1(const float* __restrict__ b1) {
    int warp = (blockIdx.x * 256 + threadIdx.x) >> 5;
    if (warp >= NN) return;
    int v = warp;
    int lane = threadIdx.x & 31;
    int slot = lane >> 2;
    int fq = lane & 3;
    const float4* h4 = (const float4*)g_h1s;
    int start = g_off[v], end = g_off[v + 1];
    float4 s = make_float4(0.f, 0.f, 0.f, 0.f);
    float4 s2 = make_float4(0.f, 0.f, 0.f, 0.f);
    int e = start + slot;
    for (; e + 8 < end; e += 16) {
        int sa = g_src[e];
        int sb = g_src[e + 8];
        float4 ha = h4[(size_t)sa * 4 + fq];
        float4 hb = h4[(size_t)sb * 4 + fq];
        s.x += ha.x; s.y += ha.y; s.z += ha.z; s.w += ha.w;
        s2.x += hb.x; s2.y += hb.y; s2.z += hb.z; s2.w += hb.w;
    }
    if (e < end) {
        float4 ha = h4[(size_t)g_src[e] * 4 + fq];
        s.x += ha.x; s.y += ha.y; s.z += ha.z; s.w += ha.w;
    }
    s.x += s2.x; s.y += s2.y; s.z += s2.z; s.w += s2.w;
#pragma unroll
    for (int o = 4; o <= 16; o <<= 1) {
        s.x += __shfl_xor_sync(0xffffffffu, s.x, o);
        s.y += __shfl_xor_sync(0xffffffffu, s.y, o);
        s.z += __shfl_xor_sync(0xffffffffu, s.z, o);
        s.w += __shfl_xor_sync(0xffffffffu, s.w, o);
    }
    float4 self = h4[(size_t)v * 4 + fq];
    float dv = g_dinv[v];
    float4 bb = ((const float4*)b1)[fq];
    float4 r;
    r.x = fmaxf((s.x + self.x) * dv + bb.x, 0.f) * dv;
    r.y = fmaxf((s.y + self.y) * dv + bb.y, 0.f) * dv;
    r.z = fmaxf((s.z + self.z) * dv + bb.z, 0.f) * dv;
    r.w = fmaxf((s.w + self.w) * dv + bb.w, 0.f) * dv;
    if (slot == 0) ((float4*)g_rs)[(size_t)v * 4 + fq] = r;
}

// Aggregation 2 fused with 16->40 GEMM + log_softmax.
__global__ __launch_bounds__(256) void k_agg2_out(const float* __restrict__ W2,
                                                 const float* __restrict__ b2,
                                                 float* __restrict__ out) {
    __shared__ float W2s[HD * NC];
    int tid = threadIdx.x;
    for (int idx = tid; idx < HD * NC; idx += 256) W2s[idx] = W2[idx];
    __syncthreads();

    int warp = (blockIdx.x * 256 + tid) >> 5;
    if (warp >= NN) return;
    int v = warp;
    int lane = tid & 31;
    int slot = lane >> 2;
    int fq = lane & 3;
    const float4* r4 = (const float4*)g_rs;
    int start = g_off[v], end = g_off[v + 1];
    float4 s = make_float4(0.f, 0.f, 0.f, 0.f);
    float4 s2 = make_float4(0.f, 0.f, 0.f, 0.f);
    int e = start + slot;
    for (; e + 8 < end; e += 16) {
        int sa = g_src[e];
        int sb = g_src[e + 8];
        float4 ha = r4[(size_t)sa * 4 + fq];
        float4 hb = r4[(size_t)sb * 4 + fq];
        s.x += ha.x; s.y += ha.y; s.z += ha.z; s.w += ha.w;
        s2.x += hb.x; s2.y += hb.y; s2.z += hb.z; s2.w += hb.w;
    }
    if (e < end) {
        float4 ha = r4[(size_t)g_src[e] * 4 + fq];
        s.x += ha.x; s.y += ha.y; s.z += ha.z; s.w += ha.w;
    }
    s.x += s2.x; s.y += s2.y; s.z += s2.z; s.w += s2.w;
#pragma unroll
    for (int o = 4; o <= 16; o <<= 1) {
        s.x += __shfl_xor_sync(0xffffffffu, s.x, o);
        s.y += __shfl_xor_sync(0xffffffffu, s.y, o);
        s.z += __shfl_xor_sync(0xffffffffu, s.z, o);
        s.w += __shfl_xor_sync(0xffffffffu, s.w, o);
    }
    float4 self = r4[(size_t)v * 4 + fq];
    float dv = g_dinv[v];
    float4 t4;
    t4.x = (s.x + self.x) * dv;
    t4.y = (s.y + self.y) * dv;
    t4.z = (s.z + self.z) * dv;
    t4.w = (s.w + self.w) * dv;

    // broadcast full 16-vector to every lane (lane q holds quad q for q<4)
    float f[16];
#pragma unroll
    for (int q = 0; q < 4; q++) {
        f[4 * q + 0] = __shfl_sync(0xffffffffu, t4.x, q);
        f[4 * q + 1] = __shfl_sync(0xffffffffu, t4.y, q);
        f[4 * q + 2] = __shfl_sync(0xffffffffu, t4.z, q);
        f[4 * q + 3] = __shfl_sync(0xffffffffu, t4.w, q);
    }

    // y = a2 @ W2 + b2 : lane holds class j0=lane, and j1=lane+32 for lane<8
    int j0 = lane;
    int j1 = lane + 32;
    bool has1 = (lane < 8);
    float acc0 = b2[j0];
    float acc1 = has1 ? b2[j1] : 0.f;
#pragma unroll
    for (int k = 0; k < 16; k++) {
        acc0 += f[k] * W2s[k * NC + j0];
        float w1v = has1 ? W2s[k * NC + j1] : 0.f;
        acc1 += f[k] * w1v;
    }

    // log_softmax over 40 classes spread across lanes
    float m = has1 ? fmaxf(acc0, acc1) : acc0;
#pragma unroll
    for (int o = 16; o >= 1; o >>= 1)
        m = fmaxf(m, __shfl_xor_sync(0xffffffffu, m, o));
    float e0 = __expf(acc0 - m);
    float e1 = has1 ? __expf(acc1 - m) : 0.f;
    float sm = e0 + e1;
#pragma unroll
    for (int o = 16; o >= 1; o >>= 1)
        sm += __shfl_xor_sync(0xffffffffu, sm, o);
    float lse = __logf(sm);
    out[(size_t)v * NC + j0] = acc0 - m - lse;
    if (has1) out[(size_t)v * NC + j1] = acc1 - m - lse;
}

// ---------------------------------------------------------------------------
extern "C" void kernel_launch(void* const* d_in, const int* in_sizes, int n_in,
                              void* d_out, int out_size) {
    const float* x  = (const float*)d_in[0];
    const void*  ei = d_in[1];
    const float* W1 = (const float*)d_in[2];
    const float* b1 = (const float*)d_in[3];
    const float* W2 = (const float*)d_in[4];
    const float* b2 = (const float*)d_in[5];
    float* out = (float*)d_out;

    k_init<<<1, 32>>>((const int*)ei);                           // #0
    k_hist<<<(NE / 4 + 255) / 256, 256>>>(ei);                   // #1
    k_scan_all<<<(NN + 1023) / 1024, 1024>>>();                  // #2
    k_gemm1<<<(NN + 31) / 32, 256>>>(x, W1);                     // #3 (profiled)
    k_scatter<<<(NE / 4 + 255) / 256, 256>>>(ei);                // #4
    k_agg1<<<(NN + 7) / 8, 256>>>(b1);                           // #5
    k_agg2_out<<<(NN + 7) / 8, 256>>>(W2, b2, out);              // #6
}